// round 2
// baseline (speedup 1.0000x reference)
#include <cuda_runtime.h>
#include <math.h>

// result = sum_{b,t} w^2 * log(sigmoid(logit)+EPS) * log_probs * (t+1) / sum(w)
// (reversed cumsum then total sum == (t+1)-weighted sum)
//
// Single fused kernel: grid-stride streaming reduction -> per-block double
// partials -> self-resetting atomic counter -> last block reduces partials and
// writes the scalar. Counter wraps back to 0 every pass => graph-replay safe,
// no zeroing kernel needed.

#define T_DIM    16384          // inner dim (power of 2)
#define EPS_F    1e-7f
#define NTHREADS 256
#define NBLOCKS  (148 * 12)     // 1776

__device__ double        g_part_t[NBLOCKS];
__device__ double        g_part_w[NBLOCKS];
__device__ unsigned int  g_count;          // zero-init at load; wraps to 0 each pass

__device__ __forceinline__ float term_elem(float lp, float lg, float w, float tscale) {
    float s = 1.0f / (1.0f + expf(-lg));
    float r = logf(s + EPS_F);
    return w * w * r * lp * tscale;
}

__device__ __forceinline__ double dbl_shfl_down(double v, int off) {
    return __shfl_down_sync(0xffffffffu, v, off);
}

__global__ void __launch_bounds__(NTHREADS)
reinforce_kernel(const float4* __restrict__ lp,
                 const float4* __restrict__ lg,
                 const float4* __restrict__ w,
                 int n4,
                 float* __restrict__ out)
{
    float acc_t = 0.0f;
    float acc_w = 0.0f;

    const int stride = gridDim.x * blockDim.x;
    for (int i = blockIdx.x * blockDim.x + threadIdx.x; i < n4; i += stride) {
        float4 a = __ldcs(&lp[i]);     // streaming: zero reuse, evict-first
        float4 b = __ldcs(&lg[i]);
        float4 c = __ldcs(&w[i]);

        // t-index of element 0 within its row (T_DIM % 4 == 0 -> same row)
        int   t0 = (i << 2) & (T_DIM - 1);
        float tw = (float)(t0 + 1);

        acc_t += term_elem(a.x, b.x, c.x, tw);
        acc_t += term_elem(a.y, b.y, c.y, tw + 1.0f);
        acc_t += term_elem(a.z, b.z, c.z, tw + 2.0f);
        acc_t += term_elem(a.w, b.w, c.w, tw + 3.0f);
        acc_w += (c.x + c.y) + (c.z + c.w);
    }

    // ---- block reduce (fp32) ----
    #pragma unroll
    for (int off = 16; off > 0; off >>= 1) {
        acc_t += __shfl_down_sync(0xffffffffu, acc_t, off);
        acc_w += __shfl_down_sync(0xffffffffu, acc_w, off);
    }

    __shared__ float st[NTHREADS / 32];
    __shared__ float sw[NTHREADS / 32];
    const int lane = threadIdx.x & 31;
    const int wid  = threadIdx.x >> 5;
    if (lane == 0) { st[wid] = acc_t; sw[wid] = acc_w; }
    __syncthreads();

    __shared__ bool s_last;
    if (threadIdx.x == 0) {
        float bt = 0.0f, bw = 0.0f;
        #pragma unroll
        for (int k = 0; k < NTHREADS / 32; k++) { bt += st[k]; bw += sw[k]; }
        g_part_t[blockIdx.x] = (double)bt;
        g_part_w[blockIdx.x] = (double)bw;
        __threadfence();
        // atomicInc with val = gridDim.x-1: old==gridDim.x-1 -> new=0 (reset)
        unsigned int prev = atomicInc(&g_count, gridDim.x - 1);
        s_last = (prev == gridDim.x - 1);
    }
    __syncthreads();

    // ---- last block: reduce all partials in double, write scalar ----
    if (s_last) {
        double dt = 0.0, dw = 0.0;
        for (int k = threadIdx.x; k < gridDim.x; k += NTHREADS) {
            dt += g_part_t[k];
            dw += g_part_w[k];
        }
        #pragma unroll
        for (int off = 16; off > 0; off >>= 1) {
            dt += dbl_shfl_down(dt, off);
            dw += dbl_shfl_down(dw, off);
        }
        __shared__ double dst[NTHREADS / 32];
        __shared__ double dsw[NTHREADS / 32];
        if (lane == 0) { dst[wid] = dt; dsw[wid] = dw; }
        __syncthreads();
        if (threadIdx.x == 0) {
            double ft = 0.0, fw = 0.0;
            #pragma unroll
            for (int k = 0; k < NTHREADS / 32; k++) { ft += dst[k]; fw += dsw[k]; }
            out[0] = (float)(ft / fw);
        }
    }
}

extern "C" void kernel_launch(void* const* d_in, const int* in_sizes, int n_in,
                              void* d_out, int out_size) {
    const float4* lp = (const float4*)d_in[0];
    const float4* lg = (const float4*)d_in[1];
    const float4* w  = (const float4*)d_in[2];
    float* out = (float*)d_out;

    const int n  = in_sizes[0];   // B*T
    const int n4 = n >> 2;

    int blocks = NBLOCKS;
    int max_blocks = (n4 + NTHREADS - 1) / NTHREADS;
    if (blocks > max_blocks) blocks = max_blocks;

    reinforce_kernel<<<blocks, NTHREADS>>>(lp, lg, w, n4, out);
}

// round 3
// speedup vs baseline: 1.3243x; 1.3243x over previous
#include <cuda_runtime.h>
#include <math.h>

// result = sum_{b,t} w^2 * log(sigmoid(logit)+EPS) * log_probs * (t+1) / sum(w)
// (reversed cumsum then total sum == (t+1)-weighted sum)
//
// Single fused kernel, self-resetting atomic counter (graph-replay safe).
// R3: fast-math intrinsics (__expf/__logf -> MUFU EX2/LG2) instead of the
// accurate libm paths; plain loads instead of __ldcs.

#define T_DIM    16384          // inner dim (power of 2)
#define EPS_F    1e-7f
#define NTHREADS 256
#define NBLOCKS  (148 * 12)     // 1776

__device__ double        g_part_t[NBLOCKS];
__device__ double        g_part_w[NBLOCKS];
__device__ unsigned int  g_count;   // zero-init at load; wraps to 0 every pass

__device__ __forceinline__ float term_elem(float lp, float lg, float w, float tscale) {
    // sigmoid via fast exp: s = 1/(1+e^{-x})
    float e = __expf(-lg);                       // FMUL + MUFU.EX2
    float s = __fdividef(1.0f, 1.0f + e);        // FADD + MUFU.RCP
    float r = __logf(s + EPS_F);                 // FADD + MUFU.LG2 + FMUL
    return w * w * r * lp * tscale;
}

__device__ __forceinline__ double dbl_shfl_down(double v, int off) {
    return __shfl_down_sync(0xffffffffu, v, off);
}

__global__ void __launch_bounds__(NTHREADS)
reinforce_kernel(const float4* __restrict__ lp,
                 const float4* __restrict__ lg,
                 const float4* __restrict__ w,
                 int n4,
                 float* __restrict__ out)
{
    float acc_t = 0.0f;
    float acc_w = 0.0f;

    const int stride = gridDim.x * blockDim.x;
    for (int i = blockIdx.x * blockDim.x + threadIdx.x; i < n4; i += stride) {
        float4 a = lp[i];
        float4 b = lg[i];
        float4 c = w[i];

        // t-index of element 0 within its row (T_DIM % 4 == 0 -> same row)
        int   t0 = (i << 2) & (T_DIM - 1);
        float tw = (float)(t0 + 1);

        acc_t += term_elem(a.x, b.x, c.x, tw);
        acc_t += term_elem(a.y, b.y, c.y, tw + 1.0f);
        acc_t += term_elem(a.z, b.z, c.z, tw + 2.0f);
        acc_t += term_elem(a.w, b.w, c.w, tw + 3.0f);
        acc_w += (c.x + c.y) + (c.z + c.w);
    }

    // ---- block reduce (fp32) ----
    #pragma unroll
    for (int off = 16; off > 0; off >>= 1) {
        acc_t += __shfl_down_sync(0xffffffffu, acc_t, off);
        acc_w += __shfl_down_sync(0xffffffffu, acc_w, off);
    }

    __shared__ float st[NTHREADS / 32];
    __shared__ float sw[NTHREADS / 32];
    const int lane = threadIdx.x & 31;
    const int wid  = threadIdx.x >> 5;
    if (lane == 0) { st[wid] = acc_t; sw[wid] = acc_w; }
    __syncthreads();

    __shared__ bool s_last;
    if (threadIdx.x == 0) {
        float bt = 0.0f, bw = 0.0f;
        #pragma unroll
        for (int k = 0; k < NTHREADS / 32; k++) { bt += st[k]; bw += sw[k]; }
        g_part_t[blockIdx.x] = (double)bt;
        g_part_w[blockIdx.x] = (double)bw;
        __threadfence();
        // atomicInc with val = gridDim.x-1: old==gridDim.x-1 -> new=0 (reset)
        unsigned int prev = atomicInc(&g_count, gridDim.x - 1);
        s_last = (prev == gridDim.x - 1);
    }
    __syncthreads();

    // ---- last block: reduce all partials in double, write scalar ----
    if (s_last) {
        double dt = 0.0, dw = 0.0;
        for (int k = threadIdx.x; k < gridDim.x; k += NTHREADS) {
            dt += g_part_t[k];
            dw += g_part_w[k];
        }
        #pragma unroll
        for (int off = 16; off > 0; off >>= 1) {
            dt += dbl_shfl_down(dt, off);
            dw += dbl_shfl_down(dw, off);
        }
        __shared__ double dst[NTHREADS / 32];
        __shared__ double dsw[NTHREADS / 32];
        if (lane == 0) { dst[wid] = dt; dsw[wid] = dw; }
        __syncthreads();
        if (threadIdx.x == 0) {
            double ft = 0.0, fw = 0.0;
            #pragma unroll
            for (int k = 0; k < NTHREADS / 32; k++) { ft += dst[k]; fw += dsw[k]; }
            out[0] = (float)(ft / fw);
        }
    }
}

extern "C" void kernel_launch(void* const* d_in, const int* in_sizes, int n_in,
                              void* d_out, int out_size) {
    const float4* lp = (const float4*)d_in[0];
    const float4* lg = (const float4*)d_in[1];
    const float4* w  = (const float4*)d_in[2];
    float* out = (float*)d_out;

    const int n  = in_sizes[0];   // B*T
    const int n4 = n >> 2;

    int blocks = NBLOCKS;
    int max_blocks = (n4 + NTHREADS - 1) / NTHREADS;
    if (blocks > max_blocks) blocks = max_blocks;

    reinforce_kernel<<<blocks, NTHREADS>>>(lp, lg, w, n4, out);
}